// round 11
// baseline (speedup 1.0000x reference)
#include <cuda_runtime.h>
#include <cuda_bf16.h>

// Problem constants (fixed by the dataset)
#define NNODES 100000
#define NEDGES 1600000
#define CAP 64   // per-node neighbor bucket; P(deg>=64)~e^-44 for Poisson(16)

// ---------------- device scratch (no allocs allowed) ----------------
__device__ float    g_bufA[NNODES * 64]; // x@gcn_w -> h2(gat)
__device__ float    g_bufB[NNODES * 64]; // gat_out(relu)
__device__ unsigned g_hi[NNODES * 32];   // packed bf16x2 hi: gcn_out -> sage mean
__device__ unsigned g_lo[NNODES * 32];   // packed bf16x2 lo (residual)
__device__ float    g_as[NNODES];
__device__ float    g_ad[NNODES];
__device__ int      g_deg[NNODES];
__device__ int      g_csr[NNODES * CAP];
__device__ int      g_is32;              // 1 if edge_index arrived as int32

__device__ __forceinline__ float lrelu(float x) { return x > 0.f ? x : 0.2f * x; }

// Decode edge_index element i, robust to int32-vs-int64 storage.
__device__ __forceinline__ int load_idx(const void* p, int i, int is32) {
    if (is32) return ((const int*)p)[i];
    return (int)((const long long*)p)[i];
}

// Split two fp32 into packed bf16x2 hi and lo (residual) parts.
__device__ __forceinline__ void split_pair(float x, float y,
                                           unsigned& hi, unsigned& lo) {
    __nv_bfloat162 h;
    h.x = __float2bfloat16_rn(x);
    h.y = __float2bfloat16_rn(y);
    hi = *reinterpret_cast<unsigned*>(&h);
    __nv_bfloat162 l;
    l.x = __float2bfloat16_rn(x - __bfloat162float(h.x));
    l.y = __float2bfloat16_rn(y - __bfloat162float(h.y));
    lo = *reinterpret_cast<unsigned*>(&l);
}

// ---------------- zero degrees + dtype sniff (fused) ----------------
// int64 layout: values < 100000 -> every odd 32-bit word (high half) is 0.
__global__ void k_zero_detect(const unsigned int* __restrict__ w, int n) {
    if (blockIdx.x == gridDim.x - 1) {
        int nz = 0;
#pragma unroll
        for (int u = 0; u < 4; u++)
            nz |= (w[2 * (threadIdx.x * 4 + u) + 1] != 0u) ? 1 : 0;
        nz = __syncthreads_or(nz);
        if (threadIdx.x == 0) g_is32 = nz;
    } else {
        int i = blockIdx.x * 256 + threadIdx.x;
        if (i < n) g_deg[i] = 0;
    }
}

// ---------------- Tensor-core GEMM body (bf16 3-product fp32 emulation) -------
// Y[n,64] = X[n,K] @ W[K,64] (+ X2 @ W2) (+bias). Error ~2^-16 per product.
// 256 thr = 8 warps; warp computes 16 rows x 64 cols via m16n8k16 mma.
// PACKED: X arrives pre-split as bf16x2 hi/lo arrays (producer-side split).

__device__ __forceinline__ void mma_bf16(float* d, const unsigned* a,
                                         unsigned b0, unsigned b1) {
    asm volatile(
        "mma.sync.aligned.m16n8k16.row.col.f32.bf16.bf16.f32 "
        "{%0,%1,%2,%3}, {%4,%5,%6,%7}, {%8,%9}, {%0,%1,%2,%3};"
        : "+f"(d[0]), "+f"(d[1]), "+f"(d[2]), "+f"(d[3])
        : "r"(a[0]), "r"(a[1]), "r"(a[2]), "r"(a[3]), "r"(b0), "r"(b1));
}

template <int K, bool DUAL, bool ATT, bool PACKED>
__device__ __forceinline__ void gemm_body(
    int bid,
    const void* __restrict__ X, const void* __restrict__ Xlo,
    const float* __restrict__ W,
    const float* __restrict__ X2, const float* __restrict__ W2,
    const float* __restrict__ bias,
    const float* __restrict__ att_s, const float* __restrict__ att_d,
    float* __restrict__ Y, int n)
{
    constexpr int KS = K / 16;
    constexpr int BSZ = 8 * KS * 2 * 32;   // fragment-packed b32 count
    __shared__ unsigned sBhi[BSZ];
    __shared__ unsigned sBlo[BSZ];
    __shared__ unsigned sB2hi[DUAL ? BSZ : 1];
    __shared__ unsigned sB2lo[DUAL ? BSZ : 1];

    int tid = threadIdx.x;

    // Stage W into mma-fragment order: b32 index ((j*KS+ks)*2+reg)*32 + lane,
    // lane = g*4+t4 holds W[k][n], W[k+1][n] with n = j*8+g, k = ks*16+reg*8+t4*2.
    for (int i = tid; i < K * 64; i += 256) {
        int k = i >> 6, nn = i & 63;
        int j = nn >> 3, g = nn & 7;
        int ks = k >> 4, reg = (k >> 3) & 1, t4 = (k >> 1) & 3, half = k & 1;
        int base = (((j * KS + ks) * 2 + reg) * 32 + g * 4 + t4) * 2 + half;
        float w = W[i];
        __nv_bfloat16 h = __float2bfloat16_rn(w);
        ((__nv_bfloat16*)sBhi)[base] = h;
        ((__nv_bfloat16*)sBlo)[base] = __float2bfloat16_rn(w - __bfloat162float(h));
        if (DUAL) {
            float w2 = W2[i];
            __nv_bfloat16 h2 = __float2bfloat16_rn(w2);
            ((__nv_bfloat16*)sB2hi)[base] = h2;
            ((__nv_bfloat16*)sB2lo)[base] = __float2bfloat16_rn(w2 - __bfloat162float(h2));
        }
    }
    __syncthreads();

    int warp = tid >> 5, lane = tid & 31;
    int g = lane >> 2, t4 = lane & 3;
    int r0 = bid * 128 + warp * 16 + g;
    int r1 = r0 + 8;
    int rr0 = min(r0, n - 1), rr1 = min(r1, n - 1);

    float acc[8][4];
#pragma unroll
    for (int j = 0; j < 8; j++)
#pragma unroll
        for (int c = 0; c < 4; c++) acc[j][c] = 0.f;

#pragma unroll
    for (int pass = 0; pass < (DUAL ? 2 : 1); pass++) {
        const unsigned* Bh = (DUAL && pass) ? sB2hi : sBhi;
        const unsigned* Bl = (DUAL && pass) ? sB2lo : sBlo;
#pragma unroll
        for (int ks = 0; ks < KS; ks++) {
            unsigned Ah[4], Al[4];
            if (PACKED && pass == 0) {
                // Pre-split: bf16x2 unit u covers features 2u,2u+1.
                const unsigned* Xh = (const unsigned*)X;
                const unsigned* Xl = (const unsigned*)Xlo;
                int u0 = ks * 8 + t4;
                Ah[0] = Xh[rr0 * (K / 2) + u0];
                Al[0] = Xl[rr0 * (K / 2) + u0];
                Ah[1] = Xh[rr1 * (K / 2) + u0];
                Al[1] = Xl[rr1 * (K / 2) + u0];
                Ah[2] = Xh[rr0 * (K / 2) + u0 + 4];
                Al[2] = Xl[rr0 * (K / 2) + u0 + 4];
                Ah[3] = Xh[rr1 * (K / 2) + u0 + 4];
                Al[3] = Xl[rr1 * (K / 2) + u0 + 4];
            } else {
                const float* Xp = (DUAL && pass) ? X2 : (const float*)X;
                int k0 = ks * 16 + t4 * 2;
                float2 x0 = *(const float2*)(Xp + rr0 * K + k0);
                float2 x1 = *(const float2*)(Xp + rr1 * K + k0);
                float2 x2v = *(const float2*)(Xp + rr0 * K + k0 + 8);
                float2 x3v = *(const float2*)(Xp + rr1 * K + k0 + 8);
                split_pair(x0.x, x0.y, Ah[0], Al[0]);
                split_pair(x1.x, x1.y, Ah[1], Al[1]);
                split_pair(x2v.x, x2v.y, Ah[2], Al[2]);
                split_pair(x3v.x, x3v.y, Ah[3], Al[3]);
            }
#pragma unroll
            for (int j = 0; j < 8; j++) {
                int bi = (j * KS + ks) * 2 * 32 + lane;
                unsigned b0h = Bh[bi], b1h = Bh[bi + 32];
                unsigned b0l = Bl[bi], b1l = Bl[bi + 32];
                mma_bf16(acc[j], Ah, b0h, b1h);   // hi*hi
                mma_bf16(acc[j], Ah, b0l, b1l);   // hi*lo
                mma_bf16(acc[j], Al, b0h, b1h);   // lo*hi
            }
        }
    }

    if (ATT) {
        float s0 = 0.f, d0 = 0.f, s1 = 0.f, d1 = 0.f;
#pragma unroll
        for (int j = 0; j < 8; j++) {
            float2 av = ((const float2*)att_s)[j * 4 + t4];
            float2 dv = ((const float2*)att_d)[j * 4 + t4];
            s0 += acc[j][0] * av.x + acc[j][1] * av.y;
            d0 += acc[j][0] * dv.x + acc[j][1] * dv.y;
            s1 += acc[j][2] * av.x + acc[j][3] * av.y;
            d1 += acc[j][2] * dv.x + acc[j][3] * dv.y;
        }
#pragma unroll
        for (int o = 1; o <= 2; o <<= 1) {
            s0 += __shfl_xor_sync(0xffffffffu, s0, o);
            d0 += __shfl_xor_sync(0xffffffffu, d0, o);
            s1 += __shfl_xor_sync(0xffffffffu, s1, o);
            d1 += __shfl_xor_sync(0xffffffffu, d1, o);
        }
        if (t4 == 0) {
            if (r0 < n) { g_as[r0] = s0; g_ad[r0] = d0; }
            if (r1 < n) { g_as[r1] = s1; g_ad[r1] = d1; }
        }
    }

#pragma unroll
    for (int j = 0; j < 8; j++) {
        float2 bv = make_float2(0.f, 0.f);
        if (bias) bv = ((const float2*)bias)[j * 4 + t4];
        acc[j][0] += bv.x; acc[j][1] += bv.y;
        acc[j][2] += bv.x; acc[j][3] += bv.y;
    }
    if (r0 < n) {
#pragma unroll
        for (int j = 0; j < 8; j++)
            *(float2*)(Y + r0 * 64 + j * 8 + t4 * 2) = make_float2(acc[j][0], acc[j][1]);
    }
    if (r1 < n) {
#pragma unroll
        for (int j = 0; j < 8; j++)
            *(float2*)(Y + r1 * 64 + j * 8 + t4 * 2) = make_float2(acc[j][2], acc[j][3]);
    }
}

template <int K, bool DUAL, bool ATT, bool PACKED>
__global__ void __launch_bounds__(256) mma_gemm(
    const void* __restrict__ X, const void* __restrict__ Xlo,
    const float* __restrict__ W,
    const float* __restrict__ X2, const float* __restrict__ W2,
    const float* __restrict__ bias,
    const float* __restrict__ att_s, const float* __restrict__ att_d,
    float* __restrict__ Y, int n)
{
    gemm_body<K, DUAL, ATT, PACKED>(blockIdx.x, X, Xlo, W, X2, W2, bias,
                                    att_s, att_d, Y, n);
}

// ---------------- fused: direct bucket CSR fill || GEMM1 (x@gcn_w) ----------
// Fill blocks first (low blockIdx) so their atomic latency chains launch early;
// GEMM1 tensor work hides them. 4 edges per thread for atomic MLP.
__global__ void __launch_bounds__(256) k_gemm1_fill(
    const float* __restrict__ X, const float* __restrict__ W,
    float* __restrict__ Y, int n,
    const void* __restrict__ ei, int ne, int fill_blocks)
{
    if ((int)blockIdx.x < fill_blocks) {
        int is32 = g_is32;
        int base = blockIdx.x * 1024;
#pragma unroll
        for (int u = 0; u < 4; u++) {
            int i = base + u * 256 + threadIdx.x;
            if (i < ne) {
                int s = load_idx(ei, i, is32);
                int d = load_idx(ei, ne + i, is32);
                int pos = atomicAdd(&g_deg[d], 1);
                g_csr[d * CAP + (pos & (CAP - 1))] = s;
            }
        }
    } else {
        gemm_body<128, false, false, false>(blockIdx.x - fill_blocks, X, nullptr,
                                            W, nullptr, nullptr, nullptr,
                                            nullptr, nullptr, Y, n);
    }
}

// ---------------- GCN aggregation: bufA -> g_hi/g_lo (norm-sum, +b, relu) ----
__global__ void k_gcn_agg(const float* __restrict__ b, int n) {
    int wid = (blockIdx.x * blockDim.x + threadIdx.x) >> 5;
    int lane = threadIdx.x & 31;
    if (wid >= n) return;
    const float2* H = (const float2*)g_bufA;
    int dc = g_deg[wid];
    float di = rsqrtf((float)(dc + 1));
    float2 hv = H[wid * 32 + lane];
    float sn = di * di;                      // self-loop norm
    float ax = hv.x * sn, ay = hv.y * sn;
    int start = wid * CAP;
    for (int base = 0; base < dc; base += 32) {
        int j = base + lane;
        int s = 0; float w = 0.f;
        if (j < dc) {
            s = g_csr[start + j];
            w = rsqrtf((float)(g_deg[s] + 1)) * di;
        }
        int cnt = min(32, dc - base);
        for (int t = 0; t < cnt; t += 4) {
            int s0 = __shfl_sync(0xffffffffu, s, t);
            int s1 = __shfl_sync(0xffffffffu, s, t + 1);
            int s2 = __shfl_sync(0xffffffffu, s, t + 2);
            int s3 = __shfl_sync(0xffffffffu, s, t + 3);
            float w0 = __shfl_sync(0xffffffffu, w, t);
            float w1 = __shfl_sync(0xffffffffu, w, t + 1);
            float w2 = __shfl_sync(0xffffffffu, w, t + 2);
            float w3 = __shfl_sync(0xffffffffu, w, t + 3);
            float2 h0 = H[s0 * 32 + lane];
            float2 h1 = H[s1 * 32 + lane];
            float2 h2 = H[s2 * 32 + lane];
            float2 h3 = H[s3 * 32 + lane];
            ax += w0 * h0.x; ay += w0 * h0.y;
            ax += w1 * h1.x; ay += w1 * h1.y;
            ax += w2 * h2.x; ay += w2 * h2.y;
            ax += w3 * h3.x; ay += w3 * h3.y;
        }
    }
    float2 bv = ((const float2*)b)[lane];
    float ox = fmaxf(ax + bv.x, 0.f);
    float oy = fmaxf(ay + bv.y, 0.f);
    unsigned hi, lo;
    split_pair(ox, oy, hi, lo);
    g_hi[wid * 32 + lane] = hi;
    g_lo[wid * 32 + lane] = lo;
}

// ---------------- GAT aggregation: bufA + a_s/a_d -> bufB ----------------
__global__ void k_gat_agg(const float* __restrict__ b, int n) {
    int wid = (blockIdx.x * blockDim.x + threadIdx.x) >> 5;
    int lane = threadIdx.x & 31;
    if (wid >= n) return;
    const float2* H = (const float2*)g_bufA;
    float adi = g_ad[wid];
    float eself = lrelu(g_as[wid] + adi);
    int start = wid * CAP;
    int dc = g_deg[wid];

    float m = eself;
    for (int base = 0; base < dc; base += 32) {
        int j = base + lane;
        float e = -1e30f;
        if (j < dc) { int s = g_csr[start + j]; e = lrelu(g_as[s] + adi); }
#pragma unroll
        for (int o = 16; o > 0; o >>= 1) e = fmaxf(e, __shfl_xor_sync(0xffffffffu, e, o));
        m = fmaxf(m, e);
    }

    float2 hv = H[wid * 32 + lane];
    float ps = __expf(eself - m);
    float ax = ps * hv.x, ay = ps * hv.y, ssum = ps;
    for (int base = 0; base < dc; base += 32) {
        int j = base + lane;
        int s = 0; float p = 0.f;
        if (j < dc) { s = g_csr[start + j]; p = __expf(lrelu(g_as[s] + adi) - m); }
        int cnt = min(32, dc - base);
        for (int t = 0; t < cnt; t += 4) {
            int s0 = __shfl_sync(0xffffffffu, s, t);
            int s1 = __shfl_sync(0xffffffffu, s, t + 1);
            int s2 = __shfl_sync(0xffffffffu, s, t + 2);
            int s3 = __shfl_sync(0xffffffffu, s, t + 3);
            float p0 = __shfl_sync(0xffffffffu, p, t);
            float p1 = __shfl_sync(0xffffffffu, p, t + 1);
            float p2 = __shfl_sync(0xffffffffu, p, t + 2);
            float p3 = __shfl_sync(0xffffffffu, p, t + 3);
            float2 h0 = H[s0 * 32 + lane];
            float2 h1 = H[s1 * 32 + lane];
            float2 h2 = H[s2 * 32 + lane];
            float2 h3 = H[s3 * 32 + lane];
            ax += p0 * h0.x; ay += p0 * h0.y;
            ax += p1 * h1.x; ay += p1 * h1.y;
            ax += p2 * h2.x; ay += p2 * h2.y;
            ax += p3 * h3.x; ay += p3 * h3.y;
            ssum += p0 + p1 + p2 + p3;
        }
    }
    float inv = 1.f / ssum;
    float2 bv = ((const float2*)b)[lane];
    float2 o;
    o.x = fmaxf(ax * inv + bv.x, 0.f);
    o.y = fmaxf(ay * inv + bv.y, 0.f);
    ((float2*)g_bufB)[wid * 32 + lane] = o;
}

// ---------------- SAGE mean (no self loops): bufB -> g_hi/g_lo --------------
__global__ void k_sage_mean(int n) {
    int wid = (blockIdx.x * blockDim.x + threadIdx.x) >> 5;
    int lane = threadIdx.x & 31;
    if (wid >= n) return;
    const float2* H = (const float2*)g_bufB;
    int start = wid * CAP;
    int dc = g_deg[wid];
    float ax = 0.f, ay = 0.f;
    for (int base = 0; base < dc; base += 32) {
        int j = base + lane;
        int s = 0; float w = 0.f;
        if (j < dc) { s = g_csr[start + j]; w = 1.f; }
        int cnt = min(32, dc - base);
        for (int t = 0; t < cnt; t += 4) {
            int s0 = __shfl_sync(0xffffffffu, s, t);
            int s1 = __shfl_sync(0xffffffffu, s, t + 1);
            int s2 = __shfl_sync(0xffffffffu, s, t + 2);
            int s3 = __shfl_sync(0xffffffffu, s, t + 3);
            float w0 = __shfl_sync(0xffffffffu, w, t);
            float w1 = __shfl_sync(0xffffffffu, w, t + 1);
            float w2 = __shfl_sync(0xffffffffu, w, t + 2);
            float w3 = __shfl_sync(0xffffffffu, w, t + 3);
            float2 h0 = H[s0 * 32 + lane];
            float2 h1 = H[s1 * 32 + lane];
            float2 h2 = H[s2 * 32 + lane];
            float2 h3 = H[s3 * 32 + lane];
            ax += w0 * h0.x; ay += w0 * h0.y;
            ax += w1 * h1.x; ay += w1 * h1.y;
            ax += w2 * h2.x; ay += w2 * h2.y;
            ax += w3 * h3.x; ay += w3 * h3.y;
        }
    }
    float invd = 1.f / fmaxf((float)dc, 1.f);
    unsigned hi, lo;
    split_pair(ax * invd, ay * invd, hi, lo);
    g_hi[wid * 32 + lane] = hi;
    g_lo[wid * 32 + lane] = lo;
}

// ---------------- launch ----------------
extern "C" void kernel_launch(void* const* d_in, const int* in_sizes, int n_in,
                              void* d_out, int out_size) {
    const float* x       = (const float*)d_in[0];
    const void*  ei      = d_in[1];
    const float* gcn_w   = (const float*)d_in[2];
    const float* gcn_b   = (const float*)d_in[3];
    const float* gat_w   = (const float*)d_in[4];
    const float* att_src = (const float*)d_in[5];
    const float* att_dst = (const float*)d_in[6];
    const float* gat_b   = (const float*)d_in[7];
    const float* sage_wl = (const float*)d_in[8];
    const float* sage_wr = (const float*)d_in[9];
    const float* sage_b  = (const float*)d_in[10];
    float*       out     = (float*)d_out;

    int n  = in_sizes[0] / 128;   // nodes
    int ne = in_sizes[1] / 2;     // edges

    void *pA = nullptr, *pB = nullptr, *pH = nullptr, *pL = nullptr;
    cudaGetSymbolAddress(&pA, g_bufA);
    cudaGetSymbolAddress(&pB, g_bufB);
    cudaGetSymbolAddress(&pH, g_hi);
    cudaGetSymbolAddress(&pL, g_lo);
    float* bufA = (float*)pA;
    float* bufB = (float*)pB;

    int gemm_blocks = (n + 127) / 128;
    int agg_blocks = (n + 7) / 8;
    int fill_blocks = (ne + 1023) / 1024;

    // Prologue: zero degrees + dtype sniff, then [CSR fill || GEMM1]
    k_zero_detect<<<(n + 255) / 256 + 1, 256>>>((const unsigned int*)ei, n);
    k_gemm1_fill<<<fill_blocks + gemm_blocks, 256>>>(
        x, gcn_w, bufA, n, ei, ne, fill_blocks);

    // Layer 1: GCN aggregation (writes packed hi/lo)
    k_gcn_agg<<<agg_blocks, 256>>>(gcn_b, n);

    // Layer 2: GAT (packed A input; att scalars fused into GEMM epilogue)
    mma_gemm<64, false, true, true><<<gemm_blocks, 256>>>(
        pH, pL, gat_w, nullptr, nullptr, nullptr, att_src, att_dst, bufA, n);
    k_gat_agg<<<agg_blocks, 256>>>(gat_b, n);

    // Layer 3: SAGE (packed mean @ Wl + fp32 gat_out @ Wr + b)
    k_sage_mean<<<agg_blocks, 256>>>(n);
    mma_gemm<64, true, false, true><<<gemm_blocks, 256>>>(
        pH, pL, sage_wl, bufB, sage_wr, sage_b, nullptr, nullptr, out, n);
}

// round 14
// speedup vs baseline: 1.1315x; 1.1315x over previous
#include <cuda_runtime.h>
#include <cuda_bf16.h>

// Problem constants (fixed by the dataset)
#define NNODES 100000
#define NEDGES 1600000
#define CAP 64   // per-node neighbor bucket; P(deg>=64)~e^-44 for Poisson(16)

// ---------------- device scratch (no allocs allowed) ----------------
__device__ __align__(16) float    g_bufA[NNODES * 64];
__device__ __align__(16) float    g_bufB[NNODES * 64];
__device__ __align__(16) unsigned g_wph[10240];  // fragment-packed W hi (b32 words)
__device__ __align__(16) unsigned g_wpl[10240];  // fragment-packed W lo
__device__ float g_as[NNODES];
__device__ float g_ad[NNODES];
__device__ int   g_deg[NNODES];
__device__ int   g_csr[NNODES * CAP];
__device__ int   g_is32;                 // 1 if edge_index arrived as int32

// Packed-W b32 offsets: gcn(K=128)=4096 words, gat/wl/wr(K=64)=2048 each
#define WOFF_GCN 0
#define WOFF_GAT 4096
#define WOFF_WL  6144
#define WOFF_WR  8192

__device__ __forceinline__ float lrelu(float x) { return x > 0.f ? x : 0.2f * x; }

__device__ __forceinline__ int load_idx(const void* p, int i, int is32) {
    if (is32) return ((const int*)p)[i];
    return (int)((const long long*)p)[i];
}

// Split two fp32 into packed bf16x2 hi and lo (residual) parts.
__device__ __forceinline__ void split_pair(float x, float y,
                                           unsigned& hi, unsigned& lo) {
    __nv_bfloat162 h;
    h.x = __float2bfloat16_rn(x);
    h.y = __float2bfloat16_rn(y);
    hi = *reinterpret_cast<unsigned*>(&h);
    __nv_bfloat162 l;
    l.x = __float2bfloat16_rn(x - __bfloat162float(h.x));
    l.y = __float2bfloat16_rn(y - __bfloat162float(h.y));
    lo = *reinterpret_cast<unsigned*>(&l);
}

// Pack one W element into fragment order:
// b32 word = ((j*KS+ks)*32 + lane)*2 + reg, bf16 half index = word*2 + half,
// where i = k*64+n, j=n>>3, g=n&7, ks=k>>4, reg=(k>>3)&1, t4=(k>>1)&3,
// half=k&1, lane=g*4+t4. reg0/reg1 adjacent -> LDS.64 in the GEMM mainloop.
__device__ __forceinline__ void pack_w(const float* __restrict__ W, int K,
                                       int i, int woff) {
    int KS = K / 16;
    int k = i >> 6, nn = i & 63;
    int j = nn >> 3, g = nn & 7;
    int ks = k >> 4, reg = (k >> 3) & 1, t4 = (k >> 1) & 3, half = k & 1;
    int lane = g * 4 + t4;
    int word = ((j * KS + ks) * 32 + lane) * 2 + reg;
    float w = W[i];
    __nv_bfloat16 h = __float2bfloat16_rn(w);
    ((__nv_bfloat16*)g_wph)[(woff + word) * 2 + half] = h;
    ((__nv_bfloat16*)g_wpl)[(woff + word) * 2 + half] =
        __float2bfloat16_rn(w - __bfloat162float(h));
}

// ---------------- zero degrees + dtype sniff + W pack (fused) ----------------
// int64 layout: values < 100000 -> every odd 32-bit word (high half) is 0.
__global__ void k_zero_detect_pack(
    const unsigned int* __restrict__ w, int n, int zb,
    const float* __restrict__ gcn_w, const float* __restrict__ gat_w,
    const float* __restrict__ sage_wl, const float* __restrict__ sage_wr)
{
    int b = blockIdx.x;
    int tid = threadIdx.x;
    if (b < zb) {
        int i = b * 256 + tid;
        if (i < n) g_deg[i] = 0;
    } else if (b == zb) {
        int nz = 0;
#pragma unroll
        for (int u = 0; u < 4; u++)
            nz |= (w[2 * (tid * 4 + u) + 1] != 0u) ? 1 : 0;
        nz = __syncthreads_or(nz);
        if (tid == 0) g_is32 = nz;
    } else {
        int pb = b - zb - 1;                 // 0..79
        if (pb < 32)       pack_w(gcn_w, 128, pb * 256 + tid, WOFF_GCN);
        else if (pb < 48)  pack_w(gat_w, 64, (pb - 32) * 256 + tid, WOFF_GAT);
        else if (pb < 64)  pack_w(sage_wl, 64, (pb - 48) * 256 + tid, WOFF_WL);
        else               pack_w(sage_wr, 64, (pb - 64) * 256 + tid, WOFF_WR);
    }
}

// ---------------- Tensor-core GEMM body (bf16 3-product fp32 emulation) -------
// Y[n,64] = X[n,K] @ W[K,64] (+ X2 @ W2) (+bias). Error ~2^-16 per product.
// 256 thr = 8 warps; warp computes 16 rows x 64 cols via m16n8k16 mma.
// W arrives pre-packed in fragment order (g_wph/g_wpl at woff).

__device__ __forceinline__ void mma_bf16(float* d, const unsigned* a,
                                         unsigned b0, unsigned b1) {
    asm volatile(
        "mma.sync.aligned.m16n8k16.row.col.f32.bf16.bf16.f32 "
        "{%0,%1,%2,%3}, {%4,%5,%6,%7}, {%8,%9}, {%0,%1,%2,%3};"
        : "+f"(d[0]), "+f"(d[1]), "+f"(d[2]), "+f"(d[3])
        : "r"(a[0]), "r"(a[1]), "r"(a[2]), "r"(a[3]), "r"(b0), "r"(b1));
}

template <int K, bool DUAL, bool ATT>
__device__ __forceinline__ void gemm_body(
    int bid,
    const float* __restrict__ X, int woff,
    const float* __restrict__ X2, int woff2,
    const float* __restrict__ bias,
    const float* __restrict__ att_s, const float* __restrict__ att_d,
    float* __restrict__ Y, int n)
{
    constexpr int KS = K / 16;
    constexpr int BSZ = 512 * KS;          // fragment-packed b32 count
    __shared__ __align__(16) unsigned sBhi[BSZ];
    __shared__ __align__(16) unsigned sBlo[BSZ];
    __shared__ __align__(16) unsigned sB2hi[DUAL ? BSZ : 4];
    __shared__ __align__(16) unsigned sB2lo[DUAL ? BSZ : 4];

    int tid = threadIdx.x;

    // Stage pre-packed W: plain vectorized copy, no conversions.
    {
        const uint4* srcH = (const uint4*)(g_wph + woff);
        const uint4* srcL = (const uint4*)(g_wpl + woff);
#pragma unroll
        for (int i = tid; i < BSZ / 4; i += 256) {
            ((uint4*)sBhi)[i] = srcH[i];
            ((uint4*)sBlo)[i] = srcL[i];
        }
        if (DUAL) {
            const uint4* s2H = (const uint4*)(g_wph + woff2);
            const uint4* s2L = (const uint4*)(g_wpl + woff2);
#pragma unroll
            for (int i = tid; i < BSZ / 4; i += 256) {
                ((uint4*)sB2hi)[i] = s2H[i];
                ((uint4*)sB2lo)[i] = s2L[i];
            }
        }
    }
    __syncthreads();

    int warp = tid >> 5, lane = tid & 31;
    int g = lane >> 2, t4 = lane & 3;
    int r0 = bid * 128 + warp * 16 + g;
    int r1 = r0 + 8;
    int rr0 = min(r0, n - 1), rr1 = min(r1, n - 1);

    float acc[8][4];
#pragma unroll
    for (int j = 0; j < 8; j++)
#pragma unroll
        for (int c = 0; c < 4; c++) acc[j][c] = 0.f;

#pragma unroll
    for (int pass = 0; pass < (DUAL ? 2 : 1); pass++) {
        const float* Xp = (DUAL && pass) ? X2 : X;
        const unsigned* Bh = (DUAL && pass) ? sB2hi : sBhi;
        const unsigned* Bl = (DUAL && pass) ? sB2lo : sBlo;
#pragma unroll
        for (int ks = 0; ks < KS; ks++) {
            int k0 = ks * 16 + t4 * 2;
            float2 x0 = *(const float2*)(Xp + rr0 * K + k0);
            float2 x1 = *(const float2*)(Xp + rr1 * K + k0);
            float2 x2v = *(const float2*)(Xp + rr0 * K + k0 + 8);
            float2 x3v = *(const float2*)(Xp + rr1 * K + k0 + 8);
            unsigned Ah[4], Al[4];
            split_pair(x0.x, x0.y, Ah[0], Al[0]);
            split_pair(x1.x, x1.y, Ah[1], Al[1]);
            split_pair(x2v.x, x2v.y, Ah[2], Al[2]);
            split_pair(x3v.x, x3v.y, Ah[3], Al[3]);
#pragma unroll
            for (int j = 0; j < 8; j++) {
                int bi2 = ((j * KS + ks) * 32 + lane) * 2;
                uint2 bh = *(const uint2*)&Bh[bi2];
                uint2 bl = *(const uint2*)&Bl[bi2];
                mma_bf16(acc[j], Ah, bh.x, bh.y);   // hi*hi
                mma_bf16(acc[j], Ah, bl.x, bl.y);   // hi*lo
                mma_bf16(acc[j], Al, bh.x, bh.y);   // lo*hi
            }
        }
    }

    if (ATT) {
        float s0 = 0.f, d0 = 0.f, s1 = 0.f, d1 = 0.f;
#pragma unroll
        for (int j = 0; j < 8; j++) {
            float2 av = ((const float2*)att_s)[j * 4 + t4];
            float2 dv = ((const float2*)att_d)[j * 4 + t4];
            s0 += acc[j][0] * av.x + acc[j][1] * av.y;
            d0 += acc[j][0] * dv.x + acc[j][1] * dv.y;
            s1 += acc[j][2] * av.x + acc[j][3] * av.y;
            d1 += acc[j][2] * dv.x + acc[j][3] * dv.y;
        }
#pragma unroll
        for (int o = 1; o <= 2; o <<= 1) {
            s0 += __shfl_xor_sync(0xffffffffu, s0, o);
            d0 += __shfl_xor_sync(0xffffffffu, d0, o);
            s1 += __shfl_xor_sync(0xffffffffu, s1, o);
            d1 += __shfl_xor_sync(0xffffffffu, d1, o);
        }
        if (t4 == 0) {
            if (r0 < n) { g_as[r0] = s0; g_ad[r0] = d0; }
            if (r1 < n) { g_as[r1] = s1; g_ad[r1] = d1; }
        }
    }

#pragma unroll
    for (int j = 0; j < 8; j++) {
        float2 bv = make_float2(0.f, 0.f);
        if (bias) bv = ((const float2*)bias)[j * 4 + t4];
        acc[j][0] += bv.x; acc[j][1] += bv.y;
        acc[j][2] += bv.x; acc[j][3] += bv.y;
    }
    if (r0 < n) {
#pragma unroll
        for (int j = 0; j < 8; j++)
            *(float2*)(Y + r0 * 64 + j * 8 + t4 * 2) = make_float2(acc[j][0], acc[j][1]);
    }
    if (r1 < n) {
#pragma unroll
        for (int j = 0; j < 8; j++)
            *(float2*)(Y + r1 * 64 + j * 8 + t4 * 2) = make_float2(acc[j][2], acc[j][3]);
    }
}

template <int K, bool DUAL, bool ATT>
__global__ void __launch_bounds__(256) mma_gemm(
    const float* __restrict__ X, int woff,
    const float* __restrict__ X2, int woff2,
    const float* __restrict__ bias,
    const float* __restrict__ att_s, const float* __restrict__ att_d,
    float* __restrict__ Y, int n)
{
    gemm_body<K, DUAL, ATT>(blockIdx.x, X, woff, X2, woff2, bias,
                            att_s, att_d, Y, n);
}

// ---------------- fused: direct bucket CSR fill || GEMM1 (x@gcn_w) ----------
__global__ void __launch_bounds__(256) k_gemm1_fill(
    const float* __restrict__ X, float* __restrict__ Y, int n,
    const void* __restrict__ ei, int ne, int fill_blocks)
{
    if ((int)blockIdx.x < fill_blocks) {
        int is32 = g_is32;
        int base = blockIdx.x * 1024;
#pragma unroll
        for (int u = 0; u < 4; u++) {
            int i = base + u * 256 + threadIdx.x;
            if (i < ne) {
                int s = load_idx(ei, i, is32);
                int d = load_idx(ei, ne + i, is32);
                int pos = atomicAdd(&g_deg[d], 1);
                g_csr[d * CAP + (pos & (CAP - 1))] = s;
            }
        }
    } else {
        gemm_body<128, false, false>(blockIdx.x - fill_blocks, X, WOFF_GCN,
                                     nullptr, 0, nullptr, nullptr, nullptr,
                                     Y, n);
    }
}

// ---------------- GCN aggregation: bufA -> bufB (norm-sum, +b, relu) ---------
__global__ void k_gcn_agg(const float* __restrict__ b, int n) {
    int wid = (blockIdx.x * blockDim.x + threadIdx.x) >> 5;
    int lane = threadIdx.x & 31;
    if (wid >= n) return;
    const float2* H = (const float2*)g_bufA;
    int dc = g_deg[wid];
    float di = rsqrtf((float)(dc + 1));
    float2 hv = H[wid * 32 + lane];
    float sn = di * di;                      // self-loop norm
    float ax = hv.x * sn, ay = hv.y * sn;
    int start = wid * CAP;
    for (int base = 0; base < dc; base += 32) {
        int j = base + lane;
        int s = 0; float w = 0.f;
        if (j < dc) {
            s = g_csr[start + j];
            w = rsqrtf((float)(g_deg[s] + 1)) * di;
        }
        int cnt = min(32, dc - base);
        for (int t = 0; t < cnt; t += 4) {
            int s0 = __shfl_sync(0xffffffffu, s, t);
            int s1 = __shfl_sync(0xffffffffu, s, t + 1);
            int s2 = __shfl_sync(0xffffffffu, s, t + 2);
            int s3 = __shfl_sync(0xffffffffu, s, t + 3);
            float w0 = __shfl_sync(0xffffffffu, w, t);
            float w1 = __shfl_sync(0xffffffffu, w, t + 1);
            float w2 = __shfl_sync(0xffffffffu, w, t + 2);
            float w3 = __shfl_sync(0xffffffffu, w, t + 3);
            float2 h0 = H[s0 * 32 + lane];
            float2 h1 = H[s1 * 32 + lane];
            float2 h2 = H[s2 * 32 + lane];
            float2 h3 = H[s3 * 32 + lane];
            ax += w0 * h0.x; ay += w0 * h0.y;
            ax += w1 * h1.x; ay += w1 * h1.y;
            ax += w2 * h2.x; ay += w2 * h2.y;
            ax += w3 * h3.x; ay += w3 * h3.y;
        }
    }
    float2 bv = ((const float2*)b)[lane];
    float2 o;
    o.x = fmaxf(ax + bv.x, 0.f);
    o.y = fmaxf(ay + bv.y, 0.f);
    ((float2*)g_bufB)[wid * 32 + lane] = o;
}

// ---------------- GAT aggregation: bufA + a_s/a_d -> bufB ----------------
__global__ void k_gat_agg(const float* __restrict__ b, int n) {
    int wid = (blockIdx.x * blockDim.x + threadIdx.x) >> 5;
    int lane = threadIdx.x & 31;
    if (wid >= n) return;
    const float2* H = (const float2*)g_bufA;
    float adi = g_ad[wid];
    float eself = lrelu(g_as[wid] + adi);
    int start = wid * CAP;
    int dc = g_deg[wid];

    float m = eself;
    for (int base = 0; base < dc; base += 32) {
        int j = base + lane;
        float e = -1e30f;
        if (j < dc) { int s = g_csr[start + j]; e = lrelu(g_as[s] + adi); }
#pragma unroll
        for (int o = 16; o > 0; o >>= 1) e = fmaxf(e, __shfl_xor_sync(0xffffffffu, e, o));
        m = fmaxf(m, e);
    }

    float2 hv = H[wid * 32 + lane];
    float ps = __expf(eself - m);
    float ax = ps * hv.x, ay = ps * hv.y, ssum = ps;
    for (int base = 0; base < dc; base += 32) {
        int j = base + lane;
        int s = 0; float p = 0.f;
        if (j < dc) { s = g_csr[start + j]; p = __expf(lrelu(g_as[s] + adi) - m); }
        int cnt = min(32, dc - base);
        for (int t = 0; t < cnt; t += 4) {
            int s0 = __shfl_sync(0xffffffffu, s, t);
            int s1 = __shfl_sync(0xffffffffu, s, t + 1);
            int s2 = __shfl_sync(0xffffffffu, s, t + 2);
            int s3 = __shfl_sync(0xffffffffu, s, t + 3);
            float p0 = __shfl_sync(0xffffffffu, p, t);
            float p1 = __shfl_sync(0xffffffffu, p, t + 1);
            float p2 = __shfl_sync(0xffffffffu, p, t + 2);
            float p3 = __shfl_sync(0xffffffffu, p, t + 3);
            float2 h0 = H[s0 * 32 + lane];
            float2 h1 = H[s1 * 32 + lane];
            float2 h2 = H[s2 * 32 + lane];
            float2 h3 = H[s3 * 32 + lane];
            ax += p0 * h0.x; ay += p0 * h0.y;
            ax += p1 * h1.x; ay += p1 * h1.y;
            ax += p2 * h2.x; ay += p2 * h2.y;
            ax += p3 * h3.x; ay += p3 * h3.y;
            ssum += p0 + p1 + p2 + p3;
        }
    }
    float inv = 1.f / ssum;
    float2 bv = ((const float2*)b)[lane];
    float2 o;
    o.x = fmaxf(ax * inv + bv.x, 0.f);
    o.y = fmaxf(ay * inv + bv.y, 0.f);
    ((float2*)g_bufB)[wid * 32 + lane] = o;
}

// ---------------- SAGE mean (no self loops): bufB -> bufA --------------------
__global__ void k_sage_mean(int n) {
    int wid = (blockIdx.x * blockDim.x + threadIdx.x) >> 5;
    int lane = threadIdx.x & 31;
    if (wid >= n) return;
    const float2* H = (const float2*)g_bufB;
    int start = wid * CAP;
    int dc = g_deg[wid];
    float ax = 0.f, ay = 0.f;
    for (int base = 0; base < dc; base += 32) {
        int j = base + lane;
        int s = 0; float w = 0.f;
        if (j < dc) { s = g_csr[start + j]; w = 1.f; }
        int cnt = min(32, dc - base);
        for (int t = 0; t < cnt; t += 4) {
            int s0 = __shfl_sync(0xffffffffu, s, t);
            int s1 = __shfl_sync(0xffffffffu, s, t + 1);
            int s2 = __shfl_sync(0xffffffffu, s, t + 2);
            int s3 = __shfl_sync(0xffffffffu, s, t + 3);
            float w0 = __shfl_sync(0xffffffffu, w, t);
            float w1 = __shfl_sync(0xffffffffu, w, t + 1);
            float w2 = __shfl_sync(0xffffffffu, w, t + 2);
            float w3 = __shfl_sync(0xffffffffu, w, t + 3);
            float2 h0 = H[s0 * 32 + lane];
            float2 h1 = H[s1 * 32 + lane];
            float2 h2 = H[s2 * 32 + lane];
            float2 h3 = H[s3 * 32 + lane];
            ax += w0 * h0.x; ay += w0 * h0.y;
            ax += w1 * h1.x; ay += w1 * h1.y;
            ax += w2 * h2.x; ay += w2 * h2.y;
            ax += w3 * h3.x; ay += w3 * h3.y;
        }
    }
    float invd = 1.f / fmaxf((float)dc, 1.f);
    float2 o; o.x = ax * invd; o.y = ay * invd;
    ((float2*)g_bufA)[wid * 32 + lane] = o;
}

// ---------------- launch ----------------
extern "C" void kernel_launch(void* const* d_in, const int* in_sizes, int n_in,
                              void* d_out, int out_size) {
    const float* x       = (const float*)d_in[0];
    const void*  ei      = d_in[1];
    const float* gcn_w   = (const float*)d_in[2];
    const float* gcn_b   = (const float*)d_in[3];
    const float* gat_w   = (const float*)d_in[4];
    const float* att_src = (const float*)d_in[5];
    const float* att_dst = (const float*)d_in[6];
    const float* gat_b   = (const float*)d_in[7];
    const float* sage_wl = (const float*)d_in[8];
    const float* sage_wr = (const float*)d_in[9];
    const float* sage_b  = (const float*)d_in[10];
    float*       out     = (float*)d_out;

    int n  = in_sizes[0] / 128;   // nodes
    int ne = in_sizes[1] / 2;     // edges

    void *pA = nullptr, *pB = nullptr;
    cudaGetSymbolAddress(&pA, g_bufA);
    cudaGetSymbolAddress(&pB, g_bufB);
    float* bufA = (float*)pA;
    float* bufB = (float*)pB;

    int gemm_blocks = (n + 127) / 128;
    int agg_blocks = (n + 7) / 8;
    int fill_blocks = (ne + 1023) / 1024;
    int zb = (n + 255) / 256;

    // Prologue: zero degrees + dtype sniff + W fragment pack (one launch),
    // then [CSR fill || GEMM1].
    k_zero_detect_pack<<<zb + 81, 256>>>((const unsigned int*)ei, n, zb,
                                         gcn_w, gat_w, sage_wl, sage_wr);
    k_gemm1_fill<<<fill_blocks + gemm_blocks, 256>>>(x, bufA, n, ei, ne,
                                                     fill_blocks);

    // Layer 1: GCN aggregation
    k_gcn_agg<<<agg_blocks, 256>>>(gcn_b, n);

    // Layer 2: GAT (att scalars fused into GEMM epilogue)
    mma_gemm<64, false, true><<<gemm_blocks, 256>>>(
        bufB, WOFF_GAT, nullptr, 0, nullptr, att_src, att_dst, bufA, n);
    k_gat_agg<<<agg_blocks, 256>>>(gat_b, n);

    // Layer 3: SAGE (dual GEMM: mean@Wl + gat_out@Wr + b)
    k_sage_mean<<<agg_blocks, 256>>>(n);
    mma_gemm<64, true, false><<<gemm_blocks, 256>>>(
        bufA, WOFF_WL, bufB, WOFF_WR, sage_b, nullptr, nullptr, out, n);
}